// round 16
// baseline (speedup 1.0000x reference)
#include <cuda_runtime.h>

// Fused: ConvTranspose3d(16->32,k3,s2,p1) + bias + BN(inference) + AvgPool2 + AvgPool2
// reduced analytically to a stride-2 3x3x3 conv with precomputed effective weights.
//
// Shapes: x (8,16,24,24,24)  w (16,32,3,3,3)  out (8,32,11,11,11)
//
// R15: R13 design (4ow x 4co per thread, packed f32x2 FFMA2, 256-thread CTAs,
// 8 cin-groups x 32 slots, 726 CTAs) with the reduction-scratch stride bug
// fixed: payload per slot row is now 8 grp x 16 floats = 128 floats, so
// SCR_STRIDE must be >= 128 (was 68 -> cross-slot corruption, rel_err 0.28).

#define CIN 16
#define COUT 32
#define DIN 24
#define OD 11
#define WS_ELEMS 13824          // 16*27*32 effective weights
#define SLOTS_PER_CTA 32
#define NCTA 726                // 23232 slots / 32
#define SCR_STRIDE 132          // floats per slot row (>=128 payload; 132%32=4 -> conflict-free)

__device__ float g_ws[WS_ELEMS];
__device__ float g_kc[COUT];

typedef unsigned long long u64;

__device__ __forceinline__ u64 splat2(float v) {
    u64 r;
    asm("mov.b64 %0, {%1, %1};" : "=l"(r) : "r"(__float_as_uint(v)));
    return r;
}
__device__ __forceinline__ void ffma2(u64& d, u64 a, u64 b) {
    asm("fma.rn.f32x2 %0, %1, %2, %0;" : "+l"(d) : "l"(a), "l"(b));
}

// Effective weights: Weff[cin,co,di,dj,dk] = sum over S(di)xS(dj)xS(dk) of w,
// S(0)={1,2}, S(1)={0,1,2}, S(2)={0}; folded with BN scale and 1/64 pool factor.
// Layout: g_ws[(cin*27+tap)*32 + co].  kc = bias*scale + beta - mean*scale.
__global__ void prep_kernel(const float* __restrict__ w,
                            const float* __restrict__ bias,
                            const float* __restrict__ gamma,
                            const float* __restrict__ beta,
                            const float* __restrict__ rmean,
                            const float* __restrict__ rvar) {
    int id = blockIdx.x * blockDim.x + threadIdx.x;
    if (id >= WS_ELEMS) return;
    int co  = id & 31;
    int tap = id >> 5;
    int cin = tap / 27;
    int r   = tap % 27;
    int di = r / 9, dj = (r % 9) / 3, dk = r % 3;

    const int cnt[3]    = {2, 3, 1};
    const int tab[3][3] = {{1, 2, 0}, {0, 1, 2}, {0, 0, 0}};

    const float* wb = w + (cin * COUT + co) * 27;
    float sum = 0.f;
    for (int a = 0; a < cnt[di]; ++a)
        for (int b = 0; b < cnt[dj]; ++b)
            for (int c = 0; c < cnt[dk]; ++c)
                sum += wb[tab[di][a] * 9 + tab[dj][b] * 3 + tab[dk][c]];

    float s = gamma[co] * rsqrtf(rvar[co] + 1e-5f);
    g_ws[tap * 32 + co] = sum * s * (1.f / 64.f);
    if (tap == 0)
        g_kc[co] = bias[co] * s + beta[co] - rmean[co] * s;
}

__global__ void __launch_bounds__(256, 4)
conv_kernel(const float* __restrict__ x, float* __restrict__ out) {
    extern __shared__ float ws[];
    {
        float4*       dst = (float4*)ws;
        const float4* src = (const float4*)g_ws;
        for (int i = threadIdx.x; i < WS_ELEMS / 4; i += blockDim.x)
            dst[i] = src[i];
    }
    __syncthreads();

    int tid = threadIdx.x;
    int grp = tid >> 5;          // cin group 0..7 (cin = 2*grp, 2*grp+1)
    int r   = tid & 31;          // output slot within CTA

    int og  = blockIdx.x * SLOTS_PER_CTA + r;   // exact fit: 726*32 = 23232
    int cg  = og & 7;            // 8 groups of 4 co
    int t   = og >> 3;
    int owg = t % 3;  t /= 3;    // ow0 in {0,4,8}; owg=2 has 3 valid ow
    int oh  = t % 11; t /= 11;
    int od  = t % 11;
    int b   = t / 11;
    int co  = cg * 4;
    int ow0 = owg * 4;

    // acc[ow'] = 2 packed f32x2 (co pair 0-1, co pair 2-3)
    u64 acc[4][2];
#pragma unroll
    for (int i = 0; i < 4; ++i) { acc[i][0] = 0ull; acc[i][1] = 0ull; }

    // 2*ow0 = 8*owg floats = 32B*owg -> float4 loads stay 16B aligned.
    const float* xbase = x + ((((b * CIN + grp * 2) * DIN + 2 * od) * DIN + 2 * oh) * DIN + 2 * ow0);
    const float* wbase = ws + co + grp * 2 * 27 * 32;

#pragma unroll
    for (int c = 0; c < 2; ++c) {
        const float* xc = xbase + c * (DIN * DIN * DIN);
        const float* wc = wbase + c * 27 * 32;
#pragma unroll
        for (int di = 0; di < 3; ++di) {
#pragma unroll
            for (int dj = 0; dj < 3; ++dj) {
                const float* xr = xc + (di * DIN + dj) * DIN;
                float4 q0 = *(const float4*)xr;        // x0..x3
                float4 q1 = *(const float4*)(xr + 4);  // x4..x7
                float  v8 = __ldg(xr + 8);             // x8 (only feeds discarded ow for owg=2; read stays in-bounds)
                u64 xs[9];
                xs[0] = splat2(q0.x); xs[1] = splat2(q0.y); xs[2] = splat2(q0.z);
                xs[3] = splat2(q0.w); xs[4] = splat2(q1.x); xs[5] = splat2(q1.y);
                xs[6] = splat2(q1.z); xs[7] = splat2(q1.w); xs[8] = splat2(v8);

                const float* wr = wc + (di * 9 + dj * 3) * 32;
#pragma unroll
                for (int dk = 0; dk < 3; ++dk) {
                    ulonglong2 wv = *(const ulonglong2*)(wr + dk * 32); // (w0,w1),(w2,w3)
#pragma unroll
                    for (int o = 0; o < 4; ++o) {
                        u64 xv = xs[2 * o + dk];
                        ffma2(acc[o][0], xv, wv.x);
                        ffma2(acc[o][1], xv, wv.y);
                    }
                }
            }
        }
    }

    // ---- in-smem tree reduction over the 8 cin groups ----
    // slot row = r*132 floats (payload 128); bank step 132%32=4 -> each 8-lane
    // STS/LDS.128 phase hits 8 distinct banks; 528B row keeps 16B alignment.
    __syncthreads();   // everyone done reading weights

    {
        ulonglong2* my = (ulonglong2*)(ws + r * SCR_STRIDE + grp * 16);
#pragma unroll
        for (int i = 0; i < 4; ++i)
            my[i] = make_ulonglong2(acc[i][0], acc[i][1]);  // 16 floats: ow-major, 4 co each
    }
    __syncthreads();

    if (grp < 4) {
        float4*       d = (float4*)(ws + r * SCR_STRIDE + grp * 16);
        const float4* s = (const float4*)(ws + r * SCR_STRIDE + (grp + 4) * 16);
#pragma unroll
        for (int i = 0; i < 4; ++i) {
            float4 a = d[i], e = s[i];
            d[i] = make_float4(a.x + e.x, a.y + e.y, a.z + e.z, a.w + e.w);
        }
    }
    __syncthreads();
    if (grp < 2) {
        float4*       d = (float4*)(ws + r * SCR_STRIDE + grp * 16);
        const float4* s = (const float4*)(ws + r * SCR_STRIDE + (grp + 2) * 16);
#pragma unroll
        for (int i = 0; i < 4; ++i) {
            float4 a = d[i], e = s[i];
            d[i] = make_float4(a.x + e.x, a.y + e.y, a.z + e.z, a.w + e.w);
        }
    }
    __syncthreads();
    if (grp == 0) {
        const float* d = ws + r * SCR_STRIDE;
        const float* s = ws + r * SCR_STRIDE + 16;
        float v[16];
#pragma unroll
        for (int i = 0; i < 16; ++i) v[i] = d[i] + s[i];

        float* op = out + (((b * COUT + co) * OD + od) * OD + oh) * OD + ow0;
        int nvalid = OD - ow0; if (nvalid > 4) nvalid = 4;
#pragma unroll
        for (int j = 0; j < 4; ++j) {
            float k = g_kc[co + j];
            float* oj = op + j * (OD * OD * OD);
            for (int o = 0; o < nvalid; ++o)
                oj[o] = v[o * 4 + j] + k;
        }
    }
}

extern "C" void kernel_launch(void* const* d_in, const int* in_sizes, int n_in,
                              void* d_out, int out_size) {
    const float* x     = (const float*)d_in[0];
    const float* w     = (const float*)d_in[1];
    const float* bias  = (const float*)d_in[2];
    const float* gamma = (const float*)d_in[3];
    const float* beta  = (const float*)d_in[4];
    const float* rmean = (const float*)d_in[5];
    const float* rvar  = (const float*)d_in[6];
    float* out = (float*)d_out;

    prep_kernel<<<(WS_ELEMS + 127) / 128, 128>>>(w, bias, gamma, beta, rmean, rvar);

    cudaFuncSetAttribute(conv_kernel, cudaFuncAttributeMaxDynamicSharedMemorySize,
                         WS_ELEMS * (int)sizeof(float));
    conv_kernel<<<NCTA, 256, WS_ELEMS * sizeof(float)>>>(x, out);
}

// round 17
// speedup vs baseline: 1.0958x; 1.0958x over previous
#include <cuda_runtime.h>

// Fused: ConvTranspose3d(16->32,k3,s2,p1) + bias + BN(inference) + AvgPool2 + AvgPool2
// reduced analytically to a stride-2 3x3x3 conv with precomputed effective weights.
//
// Shapes: x (8,16,24,24,24)  w (16,32,3,3,3)  out (8,32,11,11,11)
//
// R16: R8 base (2ow x 4co per thread, 512-thread CTAs, 8 cin-grp x 64 slots,
// 726 CTAs, (512,3)) + two targeted changes:
//   - co-pair packed f32x2 FFMA2 (24 FFMA -> 12 FFMA2 per row), with per-dk
//     splats so only 2 u64 splats are live at once (R15 kept 9 -> reg blowup)
//   - explicit 1-deep x row prefetch in a fully-unrolled 18-row loop

#define CIN 16
#define COUT 32
#define DIN 24
#define OD 11
#define WS_ELEMS 13824          // 16*27*32 effective weights
#define TOTAL_OUT_SLOTS 46464   // 8 b * 11 od * 11 oh * 6 owg * 8 cg
#define SLOTS_PER_CTA 64
#define NCTA 726                // 46464 / 64
#define SCR_STRIDE 68           // floats per slot row in reduction scratch

__device__ float g_ws[WS_ELEMS];
__device__ float g_kc[COUT];

typedef unsigned long long u64;

__device__ __forceinline__ u64 splat2(float v) {
    u64 r;
    asm("mov.b64 %0, {%1, %1};" : "=l"(r) : "r"(__float_as_uint(v)));
    return r;
}
__device__ __forceinline__ void ffma2(u64& d, u64 a, u64 b) {
    asm("fma.rn.f32x2 %0, %1, %2, %0;" : "+l"(d) : "l"(a), "l"(b));
}

// Effective weights: Weff[cin,co,di,dj,dk] = sum over S(di)xS(dj)xS(dk) of w,
// S(0)={1,2}, S(1)={0,1,2}, S(2)={0}; folded with BN scale and 1/64 pool factor.
// Layout: g_ws[(cin*27+tap)*32 + co].  kc = bias*scale + beta - mean*scale.
__global__ void prep_kernel(const float* __restrict__ w,
                            const float* __restrict__ bias,
                            const float* __restrict__ gamma,
                            const float* __restrict__ beta,
                            const float* __restrict__ rmean,
                            const float* __restrict__ rvar) {
    int id = blockIdx.x * blockDim.x + threadIdx.x;
    if (id >= WS_ELEMS) return;
    int co  = id & 31;
    int tap = id >> 5;
    int cin = tap / 27;
    int r   = tap % 27;
    int di = r / 9, dj = (r % 9) / 3, dk = r % 3;

    const int cnt[3]    = {2, 3, 1};
    const int tab[3][3] = {{1, 2, 0}, {0, 1, 2}, {0, 0, 0}};

    const float* wb = w + (cin * COUT + co) * 27;
    float sum = 0.f;
    for (int a = 0; a < cnt[di]; ++a)
        for (int b = 0; b < cnt[dj]; ++b)
            for (int c = 0; c < cnt[dk]; ++c)
                sum += wb[tab[di][a] * 9 + tab[dj][b] * 3 + tab[dk][c]];

    float s = gamma[co] * rsqrtf(rvar[co] + 1e-5f);
    g_ws[tap * 32 + co] = sum * s * (1.f / 64.f);
    if (tap == 0)
        g_kc[co] = bias[co] * s + beta[co] - rmean[co] * s;
}

__global__ void __launch_bounds__(512, 3)
conv_kernel(const float* __restrict__ x, float* __restrict__ out) {
    extern __shared__ float ws[];
    {
        float4*       dst = (float4*)ws;
        const float4* src = (const float4*)g_ws;
        for (int i = threadIdx.x; i < WS_ELEMS / 4; i += blockDim.x)
            dst[i] = src[i];
    }
    __syncthreads();

    int tid = threadIdx.x;
    int grp = tid >> 6;          // cin group 0..7 (cin = 2*grp, 2*grp+1)
    int r   = tid & 63;          // output slot within CTA

    int og  = blockIdx.x * SLOTS_PER_CTA + r;   // global output slot (exact fit)
    int cg  = og & 7;            // 8 groups of 4 co
    int t   = og >> 3;
    int owg = t % 6;  t /= 6;
    int oh  = t % 11; t /= 11;
    int od  = t % 11;
    int b   = t / 11;
    int co  = cg * 4;
    int ow0 = owg * 2;           // pair (ow0, ow0+1); ow0=10 is single

    // acc[o][p]: o = ow (0,1), p = co pair (co0co1, co2co3), packed f32x2
    u64 acc[2][2];
    acc[0][0] = 0ull; acc[0][1] = 0ull;
    acc[1][0] = 0ull; acc[1][1] = 0ull;

    // 16B-aligned: row pitch 24 floats = 96B, ow offset = 4*owg floats = 16B*owg.
    const float* xbase = x + ((((b * CIN + grp * 2) * DIN + 2 * od) * DIN + 2 * oh) * DIN + 2 * ow0);
    const float* wbase = ws + co + grp * 2 * 27 * 32;

    // Flattened 18 rows: rr -> (c = rr/9, di = (rr%9)/3, dj = rr%3)
    // x offset = c*13824 + di*576 + dj*24 ; w offset = c*864 + (di*9+dj*3)*32
    float4 q;  float v4;
    q  = *(const float4*)xbase;
    v4 = __ldg(xbase + 4);

#pragma unroll
    for (int rr = 0; rr < 18; ++rr) {
        const int c  = rr / 9;
        const int di = (rr % 9) / 3;
        const int dj = rr % 3;

        // prefetch next row's x while this row computes
        float4 qn; float v4n;
        if (rr < 17) {
            const int rn  = rr + 1;
            const int cn  = rn / 9;
            const int din = (rn % 9) / 3;
            const int djn = rn % 3;
            const float* xrn = xbase + cn * (DIN * DIN * DIN) + (din * DIN + djn) * DIN;
            qn  = *(const float4*)xrn;
            v4n = __ldg(xrn + 4);
        }

        const float* wr = wbase + c * (27 * 32) + (di * 9 + dj * 3) * 32;
#pragma unroll
        for (int dk = 0; dk < 3; ++dk) {
            ulonglong2 wv = *(const ulonglong2*)(wr + dk * 32); // (w0,w1),(w2,w3)
            float xaf = (dk == 0) ? q.x : (dk == 1) ? q.y : q.z;
            float xbf = (dk == 0) ? q.z : (dk == 1) ? q.w : v4;
            u64 xa = splat2(xaf);
            u64 xb = splat2(xbf);
            ffma2(acc[0][0], xa, wv.x);
            ffma2(acc[0][1], xa, wv.y);
            ffma2(acc[1][0], xb, wv.x);
            ffma2(acc[1][1], xb, wv.y);
        }

        if (rr < 17) { q = qn; v4 = v4n; }
    }

    // ---- in-smem tree reduction over the 8 cin groups ----
    // Payload per (slot,grp) = 8 floats (same as R8); row stride 68 floats,
    // bank step 68%32=4 -> each 8-lane STS/LDS.128 phase hits distinct banks.
    __syncthreads();   // everyone done reading weights

    {
        ulonglong2* my = (ulonglong2*)(ws + r * SCR_STRIDE + grp * 8);
        my[0] = make_ulonglong2(acc[0][0], acc[0][1]);  // ow0: co0..co3
        my[1] = make_ulonglong2(acc[1][0], acc[1][1]);  // ow1: co0..co3
    }
    __syncthreads();

    if (grp < 4) {
        float4*       d = (float4*)(ws + r * SCR_STRIDE + grp * 8);
        const float4* s = (const float4*)(ws + r * SCR_STRIDE + (grp + 4) * 8);
#pragma unroll
        for (int i = 0; i < 2; ++i) {
            float4 a = d[i], e = s[i];
            d[i] = make_float4(a.x + e.x, a.y + e.y, a.z + e.z, a.w + e.w);
        }
    }
    __syncthreads();
    if (grp < 2) {
        float4*       d = (float4*)(ws + r * SCR_STRIDE + grp * 8);
        const float4* s = (const float4*)(ws + r * SCR_STRIDE + (grp + 2) * 8);
#pragma unroll
        for (int i = 0; i < 2; ++i) {
            float4 a = d[i], e = s[i];
            d[i] = make_float4(a.x + e.x, a.y + e.y, a.z + e.z, a.w + e.w);
        }
    }
    __syncthreads();
    if (grp == 0) {
        const float* d = ws + r * SCR_STRIDE;
        const float* s = ws + r * SCR_STRIDE + 8;
        float v[8];
#pragma unroll
        for (int i = 0; i < 8; ++i) v[i] = d[i] + s[i];

        float* op = out + (((b * COUT + co) * OD + od) * OD + oh) * OD + ow0;
        bool has1 = (ow0 + 1) < OD;
#pragma unroll
        for (int j = 0; j < 4; ++j) {
            float k = g_kc[co + j];
            op[j * (OD * OD * OD)] = v[j] + k;
            if (has1) op[j * (OD * OD * OD) + 1] = v[4 + j] + k;
        }
    }
}

extern "C" void kernel_launch(void* const* d_in, const int* in_sizes, int n_in,
                              void* d_out, int out_size) {
    const float* x     = (const float*)d_in[0];
    const float* w     = (const float*)d_in[1];
    const float* bias  = (const float*)d_in[2];
    const float* gamma = (const float*)d_in[3];
    const float* beta  = (const float*)d_in[4];
    const float* rmean = (const float*)d_in[5];
    const float* rvar  = (const float*)d_in[6];
    float* out = (float*)d_out;

    prep_kernel<<<(WS_ELEMS + 127) / 128, 128>>>(w, bias, gamma, beta, rmean, rvar);

    cudaFuncSetAttribute(conv_kernel, cudaFuncAttributeMaxDynamicSharedMemorySize,
                         WS_ELEMS * (int)sizeof(float));
    conv_kernel<<<NCTA, 512, WS_ELEMS * sizeof(float)>>>(x, out);
}